// round 15
// baseline (speedup 1.0000x reference)
#include <cuda_runtime.h>
#include <cuda_fp16.h>
#include <cstdint>
#include <cstddef>

#define BB 8
#define SS 1024
#define DD 512
#define NHEAD 8
#define HDIM 64
#define FF 2048
#define ROWS (BB*SS)
#define EPSLN 1e-6f
#define QKVLD 1536
#define LDQ 72      // K/Q smem row stride (halves); conflict-free ldmatrix
#define LDV 72      // V smem row stride (halves); conflict-free ldmatrix
#define LOG2E 1.44269504089f
#define ONES2 0x3C003C00u   // half2(1.0, 1.0)

// flash smem byte offsets (Q 256 rows; K,V 8-stage rings; bias 8x256B)
#define OFF_K   (256*LDQ*2)
#define OFF_V   (OFF_K + 8*64*LDQ*2)
#define OFF_B   (OFF_V + 8*64*LDV*2)
#define FLASH_SMEM_BYTES (OFF_B + 8*256)   // 186368

// ------------------------------ scratch -------------------------------------
__device__ __half g_y[ROWS*DD];
__device__ __half g_qkv[(size_t)ROWS*QKVLD];
__device__ __half g_attn[ROWS*DD];
__device__ float  g_x[ROWS*DD];
__device__ __half g_h[ROWS*FF];
__device__ __half g_vt[(size_t)BB*NHEAD*HDIM*SS];
__device__ __half g_wqkvt[3*DD*DD];
__device__ __half g_wot[DD*DD];
__device__ __half g_w1t[DD*FF];
__device__ __half g_w2t[DD*FF];
__device__ float  g_biasl[BB*SS];

// ------------------------------ helpers -------------------------------------
__device__ __forceinline__ uint32_t smem_u32(const void* p){
    uint32_t a;
    asm("{ .reg .u64 t; cvta.to.shared.u64 t, %1; cvt.u32.u64 %0, t; }" : "=r"(a) : "l"(p));
    return a;
}
__device__ __forceinline__ void cpa16(uint32_t d, const void* s){
    asm volatile("cp.async.cg.shared.global [%0], [%1], 16;" :: "r"(d), "l"(s));
}
__device__ __forceinline__ void mma16816(float* d, const uint32_t* a,
                                         uint32_t b0, uint32_t b1){
    asm volatile("mma.sync.aligned.m16n8k16.row.col.f32.f16.f16.f32 "
        "{%0,%1,%2,%3},{%4,%5,%6,%7},{%8,%9},{%0,%1,%2,%3};"
        : "+f"(d[0]), "+f"(d[1]), "+f"(d[2]), "+f"(d[3])
        : "r"(a[0]), "r"(a[1]), "r"(a[2]), "r"(a[3]), "r"(b0), "r"(b1));
}
__device__ __forceinline__ void ldsm4(uint32_t* r, uint32_t addr){
    asm volatile("ldmatrix.sync.aligned.m8n8.x4.shared.b16 {%0,%1,%2,%3}, [%4];"
        : "=r"(r[0]), "=r"(r[1]), "=r"(r[2]), "=r"(r[3]) : "r"(addr));
}
__device__ __forceinline__ uint32_t h2pack(float a, float b){
    __half2 h = __floats2half2_rn(a, b);
    return *(uint32_t*)&h;
}
__device__ __forceinline__ uint32_t hexp2_2(uint32_t x){
    uint32_t r;
    asm("ex2.approx.f16x2 %0, %1;" : "=r"(r) : "r"(x));
    return r;
}

// --------------------- fp16 tensor-core GEMM via mma.sync -------------------
// C = alpha*A(MxK,K-major)*B(NxK,K-major)^T [+bias fp32][+resid fp32][relu]
// 4-stage cp.async ring, barrier + wait only every 2 K-chunks.
// VSPLIT: output tiles with gcol>=1024 go transposed into vtout[bn][h][t].
template<int NTILE, bool RELU, typename OT, bool VSPLIT>
__global__ __launch_bounds__(256, 2)
void hgemm(const __half* __restrict__ A, int lda,
           const __half* __restrict__ Bm, int ldb,
           OT* __restrict__ C, int ldc, int K,
           const float* __restrict__ bias,
           const float* __restrict__ resid, int ldr,
           float alpha, __half* __restrict__ vtout)
{
    constexpr int LDK = 40;
    constexpr int NFR = NTILE/16;
    extern __shared__ __half dsm[];
    uint32_t sA = smem_u32(dsm);
    uint32_t sB = sA + 4u*128*LDK*2;

    int tid = threadIdx.x;
    int wid = tid >> 5, lane = tid & 31;
    int wm = wid & 3, wn = wid >> 2;
    int m0 = wm*32, n0 = wn*(NTILE/2);
    int g = lane >> 2, tig = lane & 3;
    int l16 = lane & 15, koff = (lane >> 4) * 8;

    const __half* Ab = A + (long)blockIdx.y*128*lda;
    const __half* Bb = Bm + (long)blockIdx.x*NTILE*ldb;
    const int NC = K / 32;   // even for all K used (512, 2048)

    auto stage = [&](int c){
        int s = c & 3;
        const __half* ap = Ab + (long)c*32;
        uint32_t da = sA + (uint32_t)s*128*LDK*2;
        #pragma unroll
        for (int j = 0; j < 2; j++){
            int seg = j*256 + tid;
            int row = seg >> 2, qq = seg & 3;
            cpa16(da + (uint32_t)(row*LDK + qq*8)*2, ap + (long)row*lda + qq*8);
        }
        const __half* bp = Bb + (long)c*32;
        uint32_t db = sB + (uint32_t)s*NTILE*LDK*2;
        #pragma unroll
        for (int j = 0; j < NTILE/64; j++){
            int seg = j*256 + tid;
            int row = seg >> 2, qq = seg & 3;
            cpa16(db + (uint32_t)(row*LDK + qq*8)*2, bp + (long)row*ldb + qq*8);
        }
    };

    float acc[2][NFR][4];
    #pragma unroll
    for (int i = 0; i < 2; i++)
        #pragma unroll
        for (int j = 0; j < NFR; j++)
            #pragma unroll
            for (int e = 0; e < 4; e++) acc[i][j][e] = 0.f;

    stage(0);
    stage(1);
    asm volatile("cp.async.commit_group;" ::: "memory");

    auto compute = [&](int c){
        uint32_t Ap = sA + (uint32_t)(c & 3)*128*LDK*2;
        uint32_t Bp = sB + (uint32_t)(c & 3)*NTILE*LDK*2;
        #pragma unroll
        for (int ko = 0; ko < 32; ko += 16){
            uint32_t a[2][4];
            ldsm4(a[0], Ap + (uint32_t)((m0      + l16)*LDK + ko + koff)*2);
            ldsm4(a[1], Ap + (uint32_t)((m0 + 16 + l16)*LDK + ko + koff)*2);
            #pragma unroll
            for (int jp = 0; jp < NTILE/32; jp++){
                uint32_t br[4];
                ldsm4(br, Bp + (uint32_t)((n0 + jp*16 + l16)*LDK + ko + koff)*2);
                mma16816(acc[0][2*jp  ], a[0], br[0], br[2]);
                mma16816(acc[0][2*jp+1], a[0], br[1], br[3]);
                mma16816(acc[1][2*jp  ], a[1], br[0], br[2]);
                mma16816(acc[1][2*jp+1], a[1], br[1], br[3]);
            }
        }
    };

    for (int c = 0; c < NC; c += 2){
        asm volatile("cp.async.wait_group 0;" ::: "memory");
        __syncthreads();
        if (c + 2 < NC){
            stage(c + 2);
            stage(c + 3);
            asm volatile("cp.async.commit_group;" ::: "memory");
        }
        compute(c);
        compute(c + 1);
    }

    // ------------------------------ epilogue ---------------------------------
    int rowbase = blockIdx.y*128 + m0 + g;

    if (VSPLIT && (int)blockIdx.x*NTILE >= 1024){
        #pragma unroll
        for (int im = 0; im < 2; im++){
            int r0 = rowbase + im*16;
            int bq = r0 >> 10, t = r0 & 1023;
            #pragma unroll
            for (int jn = 0; jn < NFR; jn++){
                int gcol = blockIdx.x*NTILE + n0 + jn*8 + tig*2 - 1024;
                int nh = gcol >> 6, hh = gcol & 63;
                __half* vp = vtout + ((long)(bq*8 + nh)*64 + hh)*SS + t;
                vp[0]      = __float2half_rn(acc[im][jn][0] * alpha);
                vp[SS]     = __float2half_rn(acc[im][jn][1] * alpha);
                vp[8]      = __float2half_rn(acc[im][jn][2] * alpha);
                vp[SS + 8] = __float2half_rn(acc[im][jn][3] * alpha);
            }
        }
        return;
    }

    OT* Cb = C + (long)blockIdx.x*NTILE;
    const float* Rb = resid ? resid + (long)blockIdx.x*NTILE : nullptr;
    const float* Bi = bias  ? bias + (long)blockIdx.x*NTILE : nullptr;

    auto wr = [&](int r, int col, float v0, float v1){
        v0 *= alpha; v1 *= alpha;
        if (Bi){ v0 += Bi[col]; v1 += Bi[col+1]; }
        if (Rb){
            float2 rr = *(const float2*)(Rb + (long)r*ldr + col);
            v0 += rr.x; v1 += rr.y;
        }
        if (RELU){ v0 = fmaxf(v0, 0.f); v1 = fmaxf(v1, 0.f); }
        if (sizeof(OT) == 2){
            __half2 o = __floats2half2_rn(v0, v1);
            *(__half2*)((__half*)Cb + (long)r*ldc + col) = o;
        } else {
            float2 o; o.x = v0; o.y = v1;
            *(float2*)((float*)Cb + (long)r*ldc + col) = o;
        }
    };

    #pragma unroll
    for (int im = 0; im < 2; im++){
        int r0 = rowbase + im*16;
        #pragma unroll
        for (int jn = 0; jn < NFR; jn++){
            int col = n0 + jn*8 + tig*2;
            wr(r0,     col, acc[im][jn][0], acc[im][jn][1]);
            wr(r0 + 8, col, acc[im][jn][2], acc[im][jn][3]);
        }
    }
}

// ------------------- flash attention: fused S/softmax/PV --------------------
// grid (4 f-tiles, 64 bn), 256 threads, 1 block/SM. Q tile 256 rows (32/warp),
// t-tiles 64, 8-stage KV ring, barrier + wait_group only every 4 iterations.
__global__ __launch_bounds__(256, 1)
void flash_kernel(const __half* __restrict__ qkv, const __half* __restrict__ vt,
                  const float* __restrict__ biasl, __half* __restrict__ attn)
{
    extern __shared__ __half sm[];
    char* smb = (char*)sm;
    uint32_t sQ = smem_u32(sm);
    uint32_t sK = sQ + OFF_K;
    uint32_t sV = sQ + OFF_V;
    uint32_t sB = sQ + OFF_B;

    int tid = threadIdx.x, wid = tid >> 5, lane = tid & 31;
    int g = lane >> 2, tig = lane & 3;
    int l16 = lane & 15, koff = (lane >> 4) * 8;
    int bn = blockIdx.y, b = bn >> 3, n = bn & 7;
    int f0 = blockIdx.x * 256;

    const __half* Qg = qkv + ((long)b*SS + f0)*QKVLD + n*64;
    const __half* Kg = qkv + (long)b*SS*QKVLD + 512 + n*64;
    const __half* Vg = vt + (long)bn*HDIM*SS;
    const float*  bi = biasl + (long)b*SS;

    auto stageKV = [&](int it2){
        int s = it2 & 7;
        int t0 = it2*64;
        const __half* kp = Kg + (long)t0*QKVLD;
        uint32_t dk = sK + (uint32_t)s*64*LDQ*2;
        #pragma unroll
        for (int j = 0; j < 2; j++){
            int seg = j*256 + tid; int r = seg >> 3, c = seg & 7;
            cpa16(dk + (uint32_t)(r*LDQ + c*8)*2, kp + (long)r*QKVLD + c*8);
        }
        const __half* vp = Vg + t0;
        uint32_t dv = sV + (uint32_t)s*64*LDV*2;
        #pragma unroll
        for (int j = 0; j < 2; j++){
            int seg = j*256 + tid; int r = seg >> 3, c = seg & 7;
            cpa16(dv + (uint32_t)(r*LDV + c*8)*2, vp + (long)r*SS + c*8);
        }
        if (tid < 16)
            cpa16(sB + (uint32_t)s*256 + tid*16, bi + t0 + tid*4);
    };

    // prologue: Q (256x64) + KV tiles 0..3 in one commit group
    #pragma unroll
    for (int j = 0; j < 8; j++){
        int seg = j*256 + tid; int r = seg >> 3, c = seg & 7;
        cpa16(sQ + (uint32_t)(r*LDQ + c*8)*2, Qg + (long)r*QKVLD + c*8);
    }
    stageKV(0); stageKV(1); stageKV(2); stageKV(3);
    asm volatile("cp.async.commit_group;" ::: "memory");

    int m0 = wid*32;                 // 32 Q rows per warp
    float acc[2][8][4];
    #pragma unroll
    for (int i = 0; i < 2; i++)
        #pragma unroll
        for (int j = 0; j < 8; j++)
            #pragma unroll
            for (int e = 0; e < 4; e++) acc[i][j][e] = 0.f;
    float accL[2][4] = {{0.f,0.f,0.f,0.f},{0.f,0.f,0.f,0.f}};

    uint32_t qf[2][4][4];

    auto compute = [&](int it2){
        uint32_t Kp = sK + (uint32_t)(it2 & 7)*64*LDQ*2;
        uint32_t Vp = sV + (uint32_t)(it2 & 7)*64*LDV*2;
        const float* bp = (const float*)(smb + (OFF_B + (it2 & 7)*256));

        float sv[2][8][4];
        #pragma unroll
        for (int im = 0; im < 2; im++)
            #pragma unroll
            for (int nt = 0; nt < 8; nt++)
                #pragma unroll
                for (int e = 0; e < 4; e++) sv[im][nt][e] = 0.f;

        #pragma unroll
        for (int kc = 0; kc < 4; kc++){
            #pragma unroll
            for (int np = 0; np < 4; np++){
                uint32_t br[4];
                ldsm4(br, Kp + (uint32_t)((np*16 + l16)*LDQ + kc*16 + koff)*2);
                mma16816(sv[0][2*np  ], qf[0][kc], br[0], br[2]);
                mma16816(sv[0][2*np+1], qf[0][kc], br[1], br[3]);
                mma16816(sv[1][2*np  ], qf[1][kc], br[0], br[2]);
                mma16816(sv[1][2*np+1], qf[1][kc], br[1], br[3]);
            }
        }

        // per-kc2: exp (fp16) for 2 nt rows, then ones-MMA + PV MMAs
        #pragma unroll
        for (int kc2 = 0; kc2 < 4; kc2++){
            int nt0 = 2*kc2, nt1 = 2*kc2 + 1;
            float2 bv0 = *(const float2*)(bp + nt0*8 + tig*2);
            float2 bv1 = *(const float2*)(bp + nt1*8 + tig*2);
            uint32_t ph[2][4];
            #pragma unroll
            for (int im = 0; im < 2; im++){
                ph[im][0] = hexp2_2(h2pack(sv[im][nt0][0] + bv0.x,
                                           sv[im][nt0][1] + bv0.y));
                ph[im][1] = hexp2_2(h2pack(sv[im][nt0][2] + bv0.x,
                                           sv[im][nt0][3] + bv0.y));
                ph[im][2] = hexp2_2(h2pack(sv[im][nt1][0] + bv1.x,
                                           sv[im][nt1][1] + bv1.y));
                ph[im][3] = hexp2_2(h2pack(sv[im][nt1][2] + bv1.x,
                                           sv[im][nt1][3] + bv1.y));
            }
            mma16816(accL[0], ph[0], ONES2, ONES2);
            mma16816(accL[1], ph[1], ONES2, ONES2);
            #pragma unroll
            for (int jp = 0; jp < 4; jp++){
                uint32_t br[4];
                ldsm4(br, Vp + (uint32_t)((jp*16 + l16)*LDV + kc2*16 + koff)*2);
                mma16816(acc[0][2*jp  ], ph[0], br[0], br[2]);
                mma16816(acc[0][2*jp+1], ph[0], br[1], br[3]);
                mma16816(acc[1][2*jp  ], ph[1], br[0], br[2]);
                mma16816(acc[1][2*jp+1], ph[1], br[1], br[3]);
            }
        }
    };

    for (int it = 0; it < 16; it += 4){
        asm volatile("cp.async.wait_group 0;" ::: "memory");
        __syncthreads();
        if (it + 4 < 16){
            stageKV(it + 4); stageKV(it + 5);
            stageKV(it + 6); stageKV(it + 7);
            asm volatile("cp.async.commit_group;" ::: "memory");
        }
        if (it == 0){
            const __half2 s8 = __float2half2_rn(0.125f * LOG2E);
            #pragma unroll
            for (int im = 0; im < 2; im++)
                #pragma unroll
                for (int kc = 0; kc < 4; kc++){
                    ldsm4(qf[im][kc],
                          sQ + (uint32_t)((m0 + im*16 + l16)*LDQ + kc*16 + koff)*2);
                    #pragma unroll
                    for (int e = 0; e < 4; e++){
                        __half2 v = *(__half2*)&qf[im][kc][e];
                        v = __hmul2(v, s8);
                        qf[im][kc][e] = *(uint32_t*)&v;
                    }
                }
        }
        compute(it);
        compute(it + 1);
        compute(it + 2);
        compute(it + 3);
    }

    #pragma unroll
    for (int im = 0; im < 2; im++){
        float i0 = __frcp_rn(accL[im][0]), i1 = __frcp_rn(accL[im][2]);
        int row0 = f0 + m0 + im*16 + g;
        __half* op0 = attn + ((long)b*SS + row0    )*DD + n*64;
        __half* op1 = attn + ((long)b*SS + row0 + 8)*DD + n*64;
        #pragma unroll
        for (int jn = 0; jn < 8; jn++){
            int col = jn*8 + tig*2;
            *(__half2*)(op0 + col) = __floats2half2_rn(acc[im][jn][0]*i0,
                                                       acc[im][jn][1]*i0);
            *(__half2*)(op1 + col) = __floats2half2_rn(acc[im][jn][2]*i1,
                                                       acc[im][jn][3]*i1);
        }
    }
}

// ------- all weight transposes + bias*log2e prescale in one launch ----------
__global__ void transpose_all(const float* __restrict__ wq, const float* __restrict__ wk,
                              const float* __restrict__ wv, const float* __restrict__ wo,
                              const float* __restrict__ w1, const float* __restrict__ w2,
                              __half* __restrict__ wqkvt, __half* __restrict__ wot,
                              __half* __restrict__ w1t, __half* __restrict__ w2t,
                              const float* __restrict__ abias, float* __restrict__ biasl)
{
    __shared__ float t[32][33];
    int bid = blockIdx.x;
    if (bid >= 3072){   // bias prescale: 32 blocks x 256 threads = 8192 values
        int idx = (bid - 3072)*256 + threadIdx.y*32 + threadIdx.x;
        biasl[idx] = abias[idx] * LOG2E;
        return;
    }
    const float* in; __half* out; int ld_in, ld_out, bx, by;
    if (bid < 768){
        int s = bid >> 8, r = bid & 255;
        in = (s == 0) ? wq : (s == 1) ? wk : wv;
        out = wqkvt + (long)s*512*512;
        ld_in = 512; ld_out = 512; bx = r & 15; by = r >> 4;
    } else if (bid < 1024){
        int r = bid - 768;
        in = wo; out = wot; ld_in = 512; ld_out = 512; bx = r & 15; by = r >> 4;
    } else if (bid < 2048){
        int r = bid - 1024;
        in = w1; out = w1t; ld_in = 2048; ld_out = 512; bx = r & 63; by = r >> 6;
    } else {
        int r = bid - 2048;
        in = w2; out = w2t; ld_in = 512; ld_out = 2048; bx = r & 15; by = r >> 4;
    }
    int r0 = by*32, c0 = bx*32;
    int tx = threadIdx.x, ty = threadIdx.y;
    #pragma unroll
    for (int k = 0; k < 32; k += 8)
        t[ty+k][tx] = in[(long)(r0+ty+k)*ld_in + c0+tx];
    __syncthreads();
    #pragma unroll
    for (int k = 0; k < 32; k += 8)
        out[(long)(c0+ty+k)*ld_out + r0+tx] = __float2half_rn(t[tx][ty+k]);
}

// ---------------- LayerNorm (fp32 in -> fp16 out) -----------------------------
__global__ void ln_kernel(const float* __restrict__ in,
                          const float* __restrict__ gamma,
                          const float* __restrict__ beta,
                          __half* __restrict__ out)
{
    int row = blockIdx.x;
    const float4* x4 = (const float4*)(in + (size_t)row * DD);
    __half2* o2 = (__half2*)(out + (size_t)row * DD);
    int t = threadIdx.x;
    float4 v = x4[t];

    float s = v.x + v.y + v.z + v.w;
    #pragma unroll
    for (int o = 16; o; o >>= 1) s += __shfl_xor_sync(0xffffffffu, s, o);
    __shared__ float red1[4];
    if ((t & 31) == 0) red1[t >> 5] = s;
    __syncthreads();
    s = red1[0] + red1[1] + red1[2] + red1[3];
    float mean = s * (1.0f / DD);

    float dx = v.x - mean, dy = v.y - mean, dz = v.z - mean, dw = v.w - mean;
    float vs = dx*dx + dy*dy + dz*dz + dw*dw;
    #pragma unroll
    for (int o = 16; o; o >>= 1) vs += __shfl_xor_sync(0xffffffffu, vs, o);
    __shared__ float red2[4];
    if ((t & 31) == 0) red2[t >> 5] = vs;
    __syncthreads();
    vs = red2[0] + red2[1] + red2[2] + red2[3];
    float rstd = rsqrtf(vs * (1.0f / DD) + EPSLN);

    float4 g4 = ((const float4*)gamma)[t];
    float4 b4 = ((const float4*)beta)[t];
    o2[2*t]   = __floats2half2_rn(g4.x*dx*rstd + b4.x, g4.y*dy*rstd + b4.y);
    o2[2*t+1] = __floats2half2_rn(g4.z*dz*rstd + b4.z, g4.w*dw*rstd + b4.w);
}

// ------------------------------- launch ---------------------------------------
extern "C" void kernel_launch(void* const* d_in, const int* in_sizes, int n_in,
                              void* d_out, int out_size)
{
    const float* inputs = (const float*)d_in[0];
    const float* abias  = (const float*)d_in[1];
    const float* ln1_g  = (const float*)d_in[2];
    const float* ln1_b  = (const float*)d_in[3];
    const float* wq     = (const float*)d_in[4];
    const float* wk     = (const float*)d_in[5];
    const float* wv     = (const float*)d_in[6];
    const float* wo     = (const float*)d_in[7];
    const float* ln2_g  = (const float*)d_in[8];
    const float* ln2_b  = (const float*)d_in[9];
    const float* w1     = (const float*)d_in[10];
    const float* b1     = (const float*)d_in[11];
    const float* w2     = (const float*)d_in[12];
    const float* b2     = (const float*)d_in[13];

    __half *y,*qkv,*at,*h,*vt,*wqkvt,*wot,*w1t,*w2t;
    float *x,*biasl;
    cudaGetSymbolAddress((void**)&y,   g_y);
    cudaGetSymbolAddress((void**)&qkv, g_qkv);
    cudaGetSymbolAddress((void**)&at,  g_attn);
    cudaGetSymbolAddress((void**)&x,   g_x);
    cudaGetSymbolAddress((void**)&h,   g_h);
    cudaGetSymbolAddress((void**)&vt,  g_vt);
    cudaGetSymbolAddress((void**)&wqkvt, g_wqkvt);
    cudaGetSymbolAddress((void**)&wot, g_wot);
    cudaGetSymbolAddress((void**)&w1t, g_w1t);
    cudaGetSymbolAddress((void**)&w2t, g_w2t);
    cudaGetSymbolAddress((void**)&biasl, g_biasl);
    float* out = (float*)d_out;

    const int GEMM_SMEM  = 4 * (128 + 128) * 40 * 2;   // 81920
    const int FLASH_SMEM = FLASH_SMEM_BYTES;           // 186368
    cudaFuncSetAttribute(hgemm<128,false,__half,true >,
        cudaFuncAttributeMaxDynamicSharedMemorySize, GEMM_SMEM);
    cudaFuncSetAttribute(hgemm<128,false,float ,false>,
        cudaFuncAttributeMaxDynamicSharedMemorySize, GEMM_SMEM);
    cudaFuncSetAttribute(hgemm<128,true ,__half,false>,
        cudaFuncAttributeMaxDynamicSharedMemorySize, GEMM_SMEM);
    cudaFuncSetAttribute(flash_kernel,
        cudaFuncAttributeMaxDynamicSharedMemorySize, FLASH_SMEM);

    // LN1: inputs -> y (half)
    ln_kernel<<<ROWS, 128>>>(inputs, ln1_g, ln1_b, y);

    // all weight transposes + bias prescale, one launch
    transpose_all<<<3104, dim3(32,8)>>>(wq, wk, wv, wo, w1, w2,
                                        wqkvt, wot, w1t, w2t, abias, biasl);

    // fused QKV projection; V tiles written transposed into vt
    hgemm<128,false,__half,true><<<dim3(12,64,1), 256, GEMM_SMEM>>>(
        y, DD, wqkvt, DD, qkv, QKVLD, DD, nullptr, nullptr, 0, 1.0f, vt);

    // flash attention -> attn (half); Q tile 256, 8-stage ring
    flash_kernel<<<dim3(4,64,1), 256, FLASH_SMEM>>>(qkv, vt, biasl, at);

    // x = attn . wo + inputs  (fp32 out)
    hgemm<128,false,float,false><<<dim3(4,64,1), 256, GEMM_SMEM>>>(
        at, DD, wot, DD, x, DD, DD, nullptr, inputs, DD, 1.0f, nullptr);

    // LN2: x -> y (half)
    ln_kernel<<<ROWS, 128>>>(x, ln2_g, ln2_b, y);

    // FFN
    hgemm<128,true,__half,false><<<dim3(16,64,1), 256, GEMM_SMEM>>>(
        y, DD, w1t, DD, h, FF, DD, b1, nullptr, 0, 1.0f, nullptr);
    hgemm<128,false,float,false><<<dim3(4,64,1), 256, GEMM_SMEM>>>(
        h, FF, w2t, FF, out, DD, FF, b2, x, DD, 1.0f, nullptr);
}

// round 16
// speedup vs baseline: 1.0111x; 1.0111x over previous
#include <cuda_runtime.h>
#include <cuda_fp16.h>
#include <cstdint>
#include <cstddef>

#define BB 8
#define SS 1024
#define DD 512
#define NHEAD 8
#define HDIM 64
#define FF 2048
#define ROWS (BB*SS)
#define EPSLN 1e-6f
#define QKVLD 1536
#define LDQ 72      // K/Q smem row stride (halves); conflict-free ldmatrix
#define LDV 72      // V smem row stride (halves); conflict-free ldmatrix
#define LOG2E 1.44269504089f
#define ONES2 0x3C003C00u   // half2(1.0, 1.0)

// flash smem byte offsets (Q 256 rows; K,V 4-stage rings; bias 4x256B)
#define OFF_K   (256*LDQ*2)
#define OFF_V   (OFF_K + 4*64*LDQ*2)
#define OFF_B   (OFF_V + 4*64*LDV*2)
#define FLASH_SMEM_BYTES (OFF_B + 4*256)   // 111616

// ------------------------------ scratch -------------------------------------
__device__ __half g_y[ROWS*DD];
__device__ __half g_qkv[(size_t)ROWS*QKVLD];
__device__ __half g_attn[ROWS*DD];
__device__ float  g_x[ROWS*DD];
__device__ __half g_h[ROWS*FF];
__device__ __half g_vt[(size_t)BB*NHEAD*HDIM*SS];
__device__ __half g_wqkvt[3*DD*DD];
__device__ __half g_wot[DD*DD];
__device__ __half g_w1t[DD*FF];
__device__ __half g_w2t[DD*FF];
__device__ float  g_biasl[BB*SS];

// ------------------------------ helpers -------------------------------------
__device__ __forceinline__ uint32_t smem_u32(const void* p){
    uint32_t a;
    asm("{ .reg .u64 t; cvta.to.shared.u64 t, %1; cvt.u32.u64 %0, t; }" : "=r"(a) : "l"(p));
    return a;
}
__device__ __forceinline__ void cpa16(uint32_t d, const void* s){
    asm volatile("cp.async.cg.shared.global [%0], [%1], 16;" :: "r"(d), "l"(s));
}
__device__ __forceinline__ void mma16816(float* d, const uint32_t* a,
                                         uint32_t b0, uint32_t b1){
    asm volatile("mma.sync.aligned.m16n8k16.row.col.f32.f16.f16.f32 "
        "{%0,%1,%2,%3},{%4,%5,%6,%7},{%8,%9},{%0,%1,%2,%3};"
        : "+f"(d[0]), "+f"(d[1]), "+f"(d[2]), "+f"(d[3])
        : "r"(a[0]), "r"(a[1]), "r"(a[2]), "r"(a[3]), "r"(b0), "r"(b1));
}
__device__ __forceinline__ void ldsm4(uint32_t* r, uint32_t addr){
    asm volatile("ldmatrix.sync.aligned.m8n8.x4.shared.b16 {%0,%1,%2,%3}, [%4];"
        : "=r"(r[0]), "=r"(r[1]), "=r"(r[2]), "=r"(r[3]) : "r"(addr));
}
__device__ __forceinline__ uint32_t h2pack(float a, float b){
    __half2 h = __floats2half2_rn(a, b);
    return *(uint32_t*)&h;
}
__device__ __forceinline__ uint32_t hexp2_2(uint32_t x){
    uint32_t r;
    asm("ex2.approx.f16x2 %0, %1;" : "=r"(r) : "r"(x));
    return r;
}

// --------------------- fp16 tensor-core GEMM via mma.sync -------------------
// C = alpha*A(MxK,K-major)*B(NxK,K-major)^T [+bias fp32][+resid fp32][relu]
// 4-stage cp.async ring, barrier + wait only every 2 K-chunks.
// VSPLIT: output tiles with gcol>=1024 go transposed into vtout[bn][h][t].
template<int NTILE, bool RELU, typename OT, bool VSPLIT>
__global__ __launch_bounds__(256, 2)
void hgemm(const __half* __restrict__ A, int lda,
           const __half* __restrict__ Bm, int ldb,
           OT* __restrict__ C, int ldc, int K,
           const float* __restrict__ bias,
           const float* __restrict__ resid, int ldr,
           float alpha, __half* __restrict__ vtout)
{
    constexpr int LDK = 40;
    constexpr int NFR = NTILE/16;
    extern __shared__ __half dsm[];
    uint32_t sA = smem_u32(dsm);
    uint32_t sB = sA + 4u*128*LDK*2;

    int tid = threadIdx.x;
    int wid = tid >> 5, lane = tid & 31;
    int wm = wid & 3, wn = wid >> 2;
    int m0 = wm*32, n0 = wn*(NTILE/2);
    int g = lane >> 2, tig = lane & 3;
    int l16 = lane & 15, koff = (lane >> 4) * 8;

    const __half* Ab = A + (long)blockIdx.y*128*lda;
    const __half* Bb = Bm + (long)blockIdx.x*NTILE*ldb;
    const int NC = K / 32;   // even for all K used (512, 2048)

    auto stage = [&](int c){
        int s = c & 3;
        const __half* ap = Ab + (long)c*32;
        uint32_t da = sA + (uint32_t)s*128*LDK*2;
        #pragma unroll
        for (int j = 0; j < 2; j++){
            int seg = j*256 + tid;
            int row = seg >> 2, qq = seg & 3;
            cpa16(da + (uint32_t)(row*LDK + qq*8)*2, ap + (long)row*lda + qq*8);
        }
        const __half* bp = Bb + (long)c*32;
        uint32_t db = sB + (uint32_t)s*NTILE*LDK*2;
        #pragma unroll
        for (int j = 0; j < NTILE/64; j++){
            int seg = j*256 + tid;
            int row = seg >> 2, qq = seg & 3;
            cpa16(db + (uint32_t)(row*LDK + qq*8)*2, bp + (long)row*ldb + qq*8);
        }
    };

    float acc[2][NFR][4];
    #pragma unroll
    for (int i = 0; i < 2; i++)
        #pragma unroll
        for (int j = 0; j < NFR; j++)
            #pragma unroll
            for (int e = 0; e < 4; e++) acc[i][j][e] = 0.f;

    stage(0);
    stage(1);
    asm volatile("cp.async.commit_group;" ::: "memory");

    auto compute = [&](int c){
        uint32_t Ap = sA + (uint32_t)(c & 3)*128*LDK*2;
        uint32_t Bp = sB + (uint32_t)(c & 3)*NTILE*LDK*2;
        #pragma unroll
        for (int ko = 0; ko < 32; ko += 16){
            uint32_t a[2][4];
            ldsm4(a[0], Ap + (uint32_t)((m0      + l16)*LDK + ko + koff)*2);
            ldsm4(a[1], Ap + (uint32_t)((m0 + 16 + l16)*LDK + ko + koff)*2);
            #pragma unroll
            for (int jp = 0; jp < NTILE/32; jp++){
                uint32_t br[4];
                ldsm4(br, Bp + (uint32_t)((n0 + jp*16 + l16)*LDK + ko + koff)*2);
                mma16816(acc[0][2*jp  ], a[0], br[0], br[2]);
                mma16816(acc[0][2*jp+1], a[0], br[1], br[3]);
                mma16816(acc[1][2*jp  ], a[1], br[0], br[2]);
                mma16816(acc[1][2*jp+1], a[1], br[1], br[3]);
            }
        }
    };

    for (int c = 0; c < NC; c += 2){
        asm volatile("cp.async.wait_group 0;" ::: "memory");
        __syncthreads();
        if (c + 2 < NC){
            stage(c + 2);
            stage(c + 3);
            asm volatile("cp.async.commit_group;" ::: "memory");
        }
        compute(c);
        compute(c + 1);
    }

    // ------------------------------ epilogue ---------------------------------
    int rowbase = blockIdx.y*128 + m0 + g;

    if (VSPLIT && (int)blockIdx.x*NTILE >= 1024){
        #pragma unroll
        for (int im = 0; im < 2; im++){
            int r0 = rowbase + im*16;
            int bq = r0 >> 10, t = r0 & 1023;
            #pragma unroll
            for (int jn = 0; jn < NFR; jn++){
                int gcol = blockIdx.x*NTILE + n0 + jn*8 + tig*2 - 1024;
                int nh = gcol >> 6, hh = gcol & 63;
                __half* vp = vtout + ((long)(bq*8 + nh)*64 + hh)*SS + t;
                vp[0]      = __float2half_rn(acc[im][jn][0] * alpha);
                vp[SS]     = __float2half_rn(acc[im][jn][1] * alpha);
                vp[8]      = __float2half_rn(acc[im][jn][2] * alpha);
                vp[SS + 8] = __float2half_rn(acc[im][jn][3] * alpha);
            }
        }
        return;
    }

    OT* Cb = C + (long)blockIdx.x*NTILE;
    const float* Rb = resid ? resid + (long)blockIdx.x*NTILE : nullptr;
    const float* Bi = bias  ? bias + (long)blockIdx.x*NTILE : nullptr;

    auto wr = [&](int r, int col, float v0, float v1){
        v0 *= alpha; v1 *= alpha;
        if (Bi){ v0 += Bi[col]; v1 += Bi[col+1]; }
        if (Rb){
            float2 rr = *(const float2*)(Rb + (long)r*ldr + col);
            v0 += rr.x; v1 += rr.y;
        }
        if (RELU){ v0 = fmaxf(v0, 0.f); v1 = fmaxf(v1, 0.f); }
        if (sizeof(OT) == 2){
            __half2 o = __floats2half2_rn(v0, v1);
            *(__half2*)((__half*)Cb + (long)r*ldc + col) = o;
        } else {
            float2 o; o.x = v0; o.y = v1;
            *(float2*)((float*)Cb + (long)r*ldc + col) = o;
        }
    };

    #pragma unroll
    for (int im = 0; im < 2; im++){
        int r0 = rowbase + im*16;
        #pragma unroll
        for (int jn = 0; jn < NFR; jn++){
            int col = n0 + jn*8 + tig*2;
            wr(r0,     col, acc[im][jn][0], acc[im][jn][1]);
            wr(r0 + 8, col, acc[im][jn][2], acc[im][jn][3]);
        }
    }
}

// ------------------- flash attention: fused S/softmax/PV --------------------
// grid (4 f-tiles, 64 bn), 256 threads, 1 block/SM. Q tile 256 rows (32/warp),
// t-tiles 64, 4-stage KV ring, barrier + wait_group only every 2 iterations.
// (R14 configuration — best measured.)
__global__ __launch_bounds__(256, 1)
void flash_kernel(const __half* __restrict__ qkv, const __half* __restrict__ vt,
                  const float* __restrict__ biasl, __half* __restrict__ attn)
{
    extern __shared__ __half sm[];
    char* smb = (char*)sm;
    uint32_t sQ = smem_u32(sm);
    uint32_t sK = sQ + OFF_K;
    uint32_t sV = sQ + OFF_V;
    uint32_t sB = sQ + OFF_B;

    int tid = threadIdx.x, wid = tid >> 5, lane = tid & 31;
    int g = lane >> 2, tig = lane & 3;
    int l16 = lane & 15, koff = (lane >> 4) * 8;
    int bn = blockIdx.y, b = bn >> 3, n = bn & 7;
    int f0 = blockIdx.x * 256;

    const __half* Qg = qkv + ((long)b*SS + f0)*QKVLD + n*64;
    const __half* Kg = qkv + (long)b*SS*QKVLD + 512 + n*64;
    const __half* Vg = vt + (long)bn*HDIM*SS;
    const float*  bi = biasl + (long)b*SS;

    auto stageKV = [&](int it2, int s){
        int t0 = it2*64;
        const __half* kp = Kg + (long)t0*QKVLD;
        uint32_t dk = sK + (uint32_t)s*64*LDQ*2;
        #pragma unroll
        for (int j = 0; j < 2; j++){
            int seg = j*256 + tid; int r = seg >> 3, c = seg & 7;
            cpa16(dk + (uint32_t)(r*LDQ + c*8)*2, kp + (long)r*QKVLD + c*8);
        }
        const __half* vp = Vg + t0;
        uint32_t dv = sV + (uint32_t)s*64*LDV*2;
        #pragma unroll
        for (int j = 0; j < 2; j++){
            int seg = j*256 + tid; int r = seg >> 3, c = seg & 7;
            cpa16(dv + (uint32_t)(r*LDV + c*8)*2, vp + (long)r*SS + c*8);
        }
        if (tid < 16)
            cpa16(sB + (uint32_t)s*256 + tid*16, bi + t0 + tid*4);
    };

    // prologue: Q (256x64) + KV tiles 0,1 in one commit group
    #pragma unroll
    for (int j = 0; j < 8; j++){
        int seg = j*256 + tid; int r = seg >> 3, c = seg & 7;
        cpa16(sQ + (uint32_t)(r*LDQ + c*8)*2, Qg + (long)r*QKVLD + c*8);
    }
    stageKV(0, 0);
    stageKV(1, 1);
    asm volatile("cp.async.commit_group;" ::: "memory");

    int m0 = wid*32;                 // 32 Q rows per warp
    float acc[2][8][4];
    #pragma unroll
    for (int i = 0; i < 2; i++)
        #pragma unroll
        for (int j = 0; j < 8; j++)
            #pragma unroll
            for (int e = 0; e < 4; e++) acc[i][j][e] = 0.f;
    float accL[2][4] = {{0.f,0.f,0.f,0.f},{0.f,0.f,0.f,0.f}};

    uint32_t qf[2][4][4];

    auto compute = [&](int it2){
        uint32_t Kp = sK + (uint32_t)(it2 & 3)*64*LDQ*2;
        uint32_t Vp = sV + (uint32_t)(it2 & 3)*64*LDV*2;
        const float* bp = (const float*)(smb + (OFF_B + (it2 & 3)*256));

        float sv[2][8][4];
        #pragma unroll
        for (int im = 0; im < 2; im++)
            #pragma unroll
            for (int nt = 0; nt < 8; nt++)
                #pragma unroll
                for (int e = 0; e < 4; e++) sv[im][nt][e] = 0.f;

        #pragma unroll
        for (int kc = 0; kc < 4; kc++){
            #pragma unroll
            for (int np = 0; np < 4; np++){
                uint32_t br[4];
                ldsm4(br, Kp + (uint32_t)((np*16 + l16)*LDQ + kc*16 + koff)*2);
                mma16816(sv[0][2*np  ], qf[0][kc], br[0], br[2]);
                mma16816(sv[0][2*np+1], qf[0][kc], br[1], br[3]);
                mma16816(sv[1][2*np  ], qf[1][kc], br[0], br[2]);
                mma16816(sv[1][2*np+1], qf[1][kc], br[1], br[3]);
            }
        }

        // per-kc2: exp (fp16) for 2 nt rows, then ones-MMA + PV MMAs
        #pragma unroll
        for (int kc2 = 0; kc2 < 4; kc2++){
            int nt0 = 2*kc2, nt1 = 2*kc2 + 1;
            float2 bv0 = *(const float2*)(bp + nt0*8 + tig*2);
            float2 bv1 = *(const float2*)(bp + nt1*8 + tig*2);
            uint32_t ph[2][4];
            #pragma unroll
            for (int im = 0; im < 2; im++){
                ph[im][0] = hexp2_2(h2pack(sv[im][nt0][0] + bv0.x,
                                           sv[im][nt0][1] + bv0.y));
                ph[im][1] = hexp2_2(h2pack(sv[im][nt0][2] + bv0.x,
                                           sv[im][nt0][3] + bv0.y));
                ph[im][2] = hexp2_2(h2pack(sv[im][nt1][0] + bv1.x,
                                           sv[im][nt1][1] + bv1.y));
                ph[im][3] = hexp2_2(h2pack(sv[im][nt1][2] + bv1.x,
                                           sv[im][nt1][3] + bv1.y));
            }
            mma16816(accL[0], ph[0], ONES2, ONES2);
            mma16816(accL[1], ph[1], ONES2, ONES2);
            #pragma unroll
            for (int jp = 0; jp < 4; jp++){
                uint32_t br[4];
                ldsm4(br, Vp + (uint32_t)((jp*16 + l16)*LDV + kc2*16 + koff)*2);
                mma16816(acc[0][2*jp  ], ph[0], br[0], br[2]);
                mma16816(acc[0][2*jp+1], ph[0], br[1], br[3]);
                mma16816(acc[1][2*jp  ], ph[1], br[0], br[2]);
                mma16816(acc[1][2*jp+1], ph[1], br[1], br[3]);
            }
        }
    };

    for (int it = 0; it < 16; it += 2){
        asm volatile("cp.async.wait_group 0;" ::: "memory");
        __syncthreads();
        if (it + 2 < 16){
            stageKV(it + 2, (it + 2) & 3);
            stageKV(it + 3, (it + 3) & 3);
            asm volatile("cp.async.commit_group;" ::: "memory");
        }
        if (it == 0){
            const __half2 s8 = __float2half2_rn(0.125f * LOG2E);
            #pragma unroll
            for (int im = 0; im < 2; im++)
                #pragma unroll
                for (int kc = 0; kc < 4; kc++){
                    ldsm4(qf[im][kc],
                          sQ + (uint32_t)((m0 + im*16 + l16)*LDQ + kc*16 + koff)*2);
                    #pragma unroll
                    for (int e = 0; e < 4; e++){
                        __half2 v = *(__half2*)&qf[im][kc][e];
                        v = __hmul2(v, s8);
                        qf[im][kc][e] = *(uint32_t*)&v;
                    }
                }
        }
        compute(it);
        compute(it + 1);
    }

    #pragma unroll
    for (int im = 0; im < 2; im++){
        float i0 = __frcp_rn(accL[im][0]), i1 = __frcp_rn(accL[im][2]);
        int row0 = f0 + m0 + im*16 + g;
        __half* op0 = attn + ((long)b*SS + row0    )*DD + n*64;
        __half* op1 = attn + ((long)b*SS + row0 + 8)*DD + n*64;
        #pragma unroll
        for (int jn = 0; jn < 8; jn++){
            int col = jn*8 + tig*2;
            *(__half2*)(op0 + col) = __floats2half2_rn(acc[im][jn][0]*i0,
                                                       acc[im][jn][1]*i0);
            *(__half2*)(op1 + col) = __floats2half2_rn(acc[im][jn][2]*i1,
                                                       acc[im][jn][3]*i1);
        }
    }
}

// --- weight transposes + bias prescale + LN1 fused into ONE launch ----------
// blocks [0,3072): transposes; [3072,3104): bias*log2e; [3104,7200): LN1
__global__ void prep_all(const float* __restrict__ wq, const float* __restrict__ wk,
                         const float* __restrict__ wv, const float* __restrict__ wo,
                         const float* __restrict__ w1, const float* __restrict__ w2,
                         __half* __restrict__ wqkvt, __half* __restrict__ wot,
                         __half* __restrict__ w1t, __half* __restrict__ w2t,
                         const float* __restrict__ abias, float* __restrict__ biasl,
                         const float* __restrict__ inputs,
                         const float* __restrict__ ln1_g,
                         const float* __restrict__ ln1_b,
                         __half* __restrict__ y)
{
    int bid = blockIdx.x;
    int tid = threadIdx.y*32 + threadIdx.x;   // 0..255

    if (bid >= 3104){
        // --- LN1: two rows per block, 128 threads per row ---
        int sub = tid >> 7;           // 0/1: which row
        int t = tid & 127;            // lane within row group
        long row = (long)(bid - 3104)*2 + sub;
        const float4* x4 = (const float4*)(inputs + row*DD);
        __half2* o2 = (__half2*)(y + row*DD);
        float4 v = x4[t];

        float s = v.x + v.y + v.z + v.w;
        #pragma unroll
        for (int o = 16; o; o >>= 1) s += __shfl_xor_sync(0xffffffffu, s, o);
        __shared__ float redA[2][4];
        if ((t & 31) == 0) redA[sub][t >> 5] = s;
        __syncthreads();
        s = redA[sub][0] + redA[sub][1] + redA[sub][2] + redA[sub][3];
        float mean = s * (1.0f / DD);

        float dx = v.x - mean, dy = v.y - mean, dz = v.z - mean, dw = v.w - mean;
        float vs = dx*dx + dy*dy + dz*dz + dw*dw;
        #pragma unroll
        for (int o = 16; o; o >>= 1) vs += __shfl_xor_sync(0xffffffffu, vs, o);
        __shared__ float redB[2][4];
        if ((t & 31) == 0) redB[sub][t >> 5] = vs;
        __syncthreads();
        vs = redB[sub][0] + redB[sub][1] + redB[sub][2] + redB[sub][3];
        float rstd = rsqrtf(vs * (1.0f / DD) + EPSLN);

        float4 g4 = ((const float4*)ln1_g)[t];
        float4 b4 = ((const float4*)ln1_b)[t];
        o2[2*t]   = __floats2half2_rn(g4.x*dx*rstd + b4.x, g4.y*dy*rstd + b4.y);
        o2[2*t+1] = __floats2half2_rn(g4.z*dz*rstd + b4.z, g4.w*dw*rstd + b4.w);
        return;
    }
    if (bid >= 3072){
        int idx = (bid - 3072)*256 + tid;
        biasl[idx] = abias[idx] * LOG2E;
        return;
    }

    __shared__ float t[32][33];
    const float* in; __half* out; int ld_in, ld_out, bx, by;
    if (bid < 768){
        int s = bid >> 8, r = bid & 255;
        in = (s == 0) ? wq : (s == 1) ? wk : wv;
        out = wqkvt + (long)s*512*512;
        ld_in = 512; ld_out = 512; bx = r & 15; by = r >> 4;
    } else if (bid < 1024){
        int r = bid - 768;
        in = wo; out = wot; ld_in = 512; ld_out = 512; bx = r & 15; by = r >> 4;
    } else if (bid < 2048){
        int r = bid - 1024;
        in = w1; out = w1t; ld_in = 2048; ld_out = 512; bx = r & 63; by = r >> 6;
    } else {
        int r = bid - 2048;
        in = w2; out = w2t; ld_in = 512; ld_out = 2048; bx = r & 15; by = r >> 4;
    }
    int r0 = by*32, c0 = bx*32;
    int tx = threadIdx.x, ty = threadIdx.y;
    #pragma unroll
    for (int k = 0; k < 32; k += 8)
        t[ty+k][tx] = in[(long)(r0+ty+k)*ld_in + c0+tx];
    __syncthreads();
    #pragma unroll
    for (int k = 0; k < 32; k += 8)
        out[(long)(c0+ty+k)*ld_out + r0+tx] = __float2half_rn(t[tx][ty+k]);
}

// ---------------- LayerNorm (fp32 in -> fp16 out) -----------------------------
__global__ void ln_kernel(const float* __restrict__ in,
                          const float* __restrict__ gamma,
                          const float* __restrict__ beta,
                          __half* __restrict__ out)
{
    int row = blockIdx.x;
    const float4* x4 = (const float4*)(in + (size_t)row * DD);
    __half2* o2 = (__half2*)(out + (size_t)row * DD);
    int t = threadIdx.x;
    float4 v = x4[t];

    float s = v.x + v.y + v.z + v.w;
    #pragma unroll
    for (int o = 16; o; o >>= 1) s += __shfl_xor_sync(0xffffffffu, s, o);
    __shared__ float red1[4];
    if ((t & 31) == 0) red1[t >> 5] = s;
    __syncthreads();
    s = red1[0] + red1[1] + red1[2] + red1[3];
    float mean = s * (1.0f / DD);

    float dx = v.x - mean, dy = v.y - mean, dz = v.z - mean, dw = v.w - mean;
    float vs = dx*dx + dy*dy + dz*dz + dw*dw;
    #pragma unroll
    for (int o = 16; o; o >>= 1) vs += __shfl_xor_sync(0xffffffffu, vs, o);
    __shared__ float red2[4];
    if ((t & 31) == 0) red2[t >> 5] = vs;
    __syncthreads();
    vs = red2[0] + red2[1] + red2[2] + red2[3];
    float rstd = rsqrtf(vs * (1.0f / DD) + EPSLN);

    float4 g4 = ((const float4*)gamma)[t];
    float4 b4 = ((const float4*)beta)[t];
    o2[2*t]   = __floats2half2_rn(g4.x*dx*rstd + b4.x, g4.y*dy*rstd + b4.y);
    o2[2*t+1] = __floats2half2_rn(g4.z*dz*rstd + b4.z, g4.w*dw*rstd + b4.w);
}

// ------------------------------- launch ---------------------------------------
extern "C" void kernel_launch(void* const* d_in, const int* in_sizes, int n_in,
                              void* d_out, int out_size)
{
    const float* inputs = (const float*)d_in[0];
    const float* abias  = (const float*)d_in[1];
    const float* ln1_g  = (const float*)d_in[2];
    const float* ln1_b  = (const float*)d_in[3];
    const float* wq     = (const float*)d_in[4];
    const float* wk     = (const float*)d_in[5];
    const float* wv     = (const float*)d_in[6];
    const float* wo     = (const float*)d_in[7];
    const float* ln2_g  = (const float*)d_in[8];
    const float* ln2_b  = (const float*)d_in[9];
    const float* w1     = (const float*)d_in[10];
    const float* b1     = (const float*)d_in[11];
    const float* w2     = (const float*)d_in[12];
    const float* b2     = (const float*)d_in[13];

    __half *y,*qkv,*at,*h,*vt,*wqkvt,*wot,*w1t,*w2t;
    float *x,*biasl;
    cudaGetSymbolAddress((void**)&y,   g_y);
    cudaGetSymbolAddress((void**)&qkv, g_qkv);
    cudaGetSymbolAddress((void**)&at,  g_attn);
    cudaGetSymbolAddress((void**)&x,   g_x);
    cudaGetSymbolAddress((void**)&h,   g_h);
    cudaGetSymbolAddress((void**)&vt,  g_vt);
    cudaGetSymbolAddress((void**)&wqkvt, g_wqkvt);
    cudaGetSymbolAddress((void**)&wot, g_wot);
    cudaGetSymbolAddress((void**)&w1t, g_w1t);
    cudaGetSymbolAddress((void**)&w2t, g_w2t);
    cudaGetSymbolAddress((void**)&biasl, g_biasl);
    float* out = (float*)d_out;

    const int GEMM_SMEM  = 4 * (128 + 128) * 40 * 2;   // 81920
    const int FLASH_SMEM = FLASH_SMEM_BYTES;           // 111616
    cudaFuncSetAttribute(hgemm<128,false,__half,true >,
        cudaFuncAttributeMaxDynamicSharedMemorySize, GEMM_SMEM);
    cudaFuncSetAttribute(hgemm<128,false,float ,false>,
        cudaFuncAttributeMaxDynamicSharedMemorySize, GEMM_SMEM);
    cudaFuncSetAttribute(hgemm<128,true ,__half,false>,
        cudaFuncAttributeMaxDynamicSharedMemorySize, GEMM_SMEM);
    cudaFuncSetAttribute(flash_kernel,
        cudaFuncAttributeMaxDynamicSharedMemorySize, FLASH_SMEM);

    // transposes + bias prescale + LN1, one launch
    prep_all<<<7200, dim3(32,8)>>>(wq, wk, wv, wo, w1, w2,
                                   wqkvt, wot, w1t, w2t, abias, biasl,
                                   inputs, ln1_g, ln1_b, y);

    // fused QKV projection; V tiles written transposed into vt
    hgemm<128,false,__half,true><<<dim3(12,64,1), 256, GEMM_SMEM>>>(
        y, DD, wqkvt, DD, qkv, QKVLD, DD, nullptr, nullptr, 0, 1.0f, vt);

    // flash attention -> attn (half); Q tile 256, 4-stage ring (R14 config)
    flash_kernel<<<dim3(4,64,1), 256, FLASH_SMEM>>>(qkv, vt, biasl, at);

    // x = attn . wo + inputs  (fp32 out)
    hgemm<128,false,float,false><<<dim3(4,64,1), 256, GEMM_SMEM>>>(
        at, DD, wot, DD, x, DD, DD, nullptr, inputs, DD, 1.0f, nullptr);

    // LN2: x -> y (half)
    ln_kernel<<<ROWS, 128>>>(x, ln2_g, ln2_b, y);

    // FFN
    hgemm<128,true,__half,false><<<dim3(16,64,1), 256, GEMM_SMEM>>>(
        y, DD, w1t, DD, h, FF, DD, b1, nullptr, 0, 1.0f, nullptr);
    hgemm<128,false,float,false><<<dim3(4,64,1), 256, GEMM_SMEM>>>(
        h, FF, w2t, FF, out, DD, FF, b2, x, DD, 1.0f, nullptr);
}

// round 17
// speedup vs baseline: 1.0117x; 1.0005x over previous
#include <cuda_runtime.h>
#include <cuda_fp16.h>
#include <cstdint>
#include <cstddef>

#define BB 8
#define SS 1024
#define DD 512
#define NHEAD 8
#define HDIM 64
#define FF 2048
#define ROWS (BB*SS)
#define EPSLN 1e-6f
#define QKVLD 1536
#define LDQ 72      // K/Q smem row stride (halves); conflict-free ldmatrix
#define LDV 72      // V smem row stride (halves); conflict-free ldmatrix
#define LOG2E 1.44269504089f
#define ONES2 0x3C003C00u   // half2(1.0, 1.0)

// flash smem byte offsets (Q 256 rows; K,V 4-stage rings; bias 4x256B)
#define OFF_K   (256*LDQ*2)
#define OFF_V   (OFF_K + 4*64*LDQ*2)
#define OFF_B   (OFF_V + 4*64*LDV*2)
#define FLASH_SMEM_BYTES (OFF_B + 4*256)   // 111616

// ------------------------------ scratch -------------------------------------
__device__ __half g_y[ROWS*DD];
__device__ __half g_qkv[(size_t)ROWS*QKVLD];
__device__ __half g_attn[ROWS*DD];
__device__ __half g_xh[ROWS*DD];          // fp16 residual spine
__device__ __half g_h[ROWS*FF];
__device__ __half g_vt[(size_t)BB*NHEAD*HDIM*SS];
__device__ __half g_wqkvt[3*DD*DD];
__device__ __half g_wot[DD*DD];
__device__ __half g_w1t[DD*FF];
__device__ __half g_w2t[DD*FF];
__device__ float  g_biasl[BB*SS];

// ------------------------------ helpers -------------------------------------
__device__ __forceinline__ uint32_t smem_u32(const void* p){
    uint32_t a;
    asm("{ .reg .u64 t; cvta.to.shared.u64 t, %1; cvt.u32.u64 %0, t; }" : "=r"(a) : "l"(p));
    return a;
}
__device__ __forceinline__ void cpa16(uint32_t d, const void* s){
    asm volatile("cp.async.cg.shared.global [%0], [%1], 16;" :: "r"(d), "l"(s));
}
__device__ __forceinline__ void mma16816(float* d, const uint32_t* a,
                                         uint32_t b0, uint32_t b1){
    asm volatile("mma.sync.aligned.m16n8k16.row.col.f32.f16.f16.f32 "
        "{%0,%1,%2,%3},{%4,%5,%6,%7},{%8,%9},{%0,%1,%2,%3};"
        : "+f"(d[0]), "+f"(d[1]), "+f"(d[2]), "+f"(d[3])
        : "r"(a[0]), "r"(a[1]), "r"(a[2]), "r"(a[3]), "r"(b0), "r"(b1));
}
__device__ __forceinline__ void ldsm4(uint32_t* r, uint32_t addr){
    asm volatile("ldmatrix.sync.aligned.m8n8.x4.shared.b16 {%0,%1,%2,%3}, [%4];"
        : "=r"(r[0]), "=r"(r[1]), "=r"(r[2]), "=r"(r[3]) : "r"(addr));
}
__device__ __forceinline__ uint32_t h2pack(float a, float b){
    __half2 h = __floats2half2_rn(a, b);
    return *(uint32_t*)&h;
}
__device__ __forceinline__ uint32_t hexp2_2(uint32_t x){
    uint32_t r;
    asm("ex2.approx.f16x2 %0, %1;" : "=r"(r) : "r"(x));
    return r;
}

// --------------------- fp16 tensor-core GEMM via mma.sync -------------------
// C = alpha*A(MxK,K-major)*B(NxK,K-major)^T [+bias fp32][+resid RT][relu]
// 4-stage cp.async ring, barrier + wait only every 2 K-chunks.
// VSPLIT: output tiles with gcol>=1024 go transposed into vtout[bn][h][t].
template<int NTILE, bool RELU, typename OT, typename RT, bool VSPLIT>
__global__ __launch_bounds__(256, 2)
void hgemm(const __half* __restrict__ A, int lda,
           const __half* __restrict__ Bm, int ldb,
           OT* __restrict__ C, int ldc, int K,
           const float* __restrict__ bias,
           const RT* __restrict__ resid, int ldr,
           float alpha, __half* __restrict__ vtout)
{
    constexpr int LDK = 40;
    constexpr int NFR = NTILE/16;
    extern __shared__ __half dsm[];
    uint32_t sA = smem_u32(dsm);
    uint32_t sB = sA + 4u*128*LDK*2;

    int tid = threadIdx.x;
    int wid = tid >> 5, lane = tid & 31;
    int wm = wid & 3, wn = wid >> 2;
    int m0 = wm*32, n0 = wn*(NTILE/2);
    int g = lane >> 2, tig = lane & 3;
    int l16 = lane & 15, koff = (lane >> 4) * 8;

    const __half* Ab = A + (long)blockIdx.y*128*lda;
    const __half* Bb = Bm + (long)blockIdx.x*NTILE*ldb;
    const int NC = K / 32;

    auto stage = [&](int c){
        int s = c & 3;
        const __half* ap = Ab + (long)c*32;
        uint32_t da = sA + (uint32_t)s*128*LDK*2;
        #pragma unroll
        for (int j = 0; j < 2; j++){
            int seg = j*256 + tid;
            int row = seg >> 2, qq = seg & 3;
            cpa16(da + (uint32_t)(row*LDK + qq*8)*2, ap + (long)row*lda + qq*8);
        }
        const __half* bp = Bb + (long)c*32;
        uint32_t db = sB + (uint32_t)s*NTILE*LDK*2;
        #pragma unroll
        for (int j = 0; j < NTILE/64; j++){
            int seg = j*256 + tid;
            int row = seg >> 2, qq = seg & 3;
            cpa16(db + (uint32_t)(row*LDK + qq*8)*2, bp + (long)row*ldb + qq*8);
        }
    };

    float acc[2][NFR][4];
    #pragma unroll
    for (int i = 0; i < 2; i++)
        #pragma unroll
        for (int j = 0; j < NFR; j++)
            #pragma unroll
            for (int e = 0; e < 4; e++) acc[i][j][e] = 0.f;

    stage(0);
    stage(1);
    asm volatile("cp.async.commit_group;" ::: "memory");

    auto compute = [&](int c){
        uint32_t Ap = sA + (uint32_t)(c & 3)*128*LDK*2;
        uint32_t Bp = sB + (uint32_t)(c & 3)*NTILE*LDK*2;
        #pragma unroll
        for (int ko = 0; ko < 32; ko += 16){
            uint32_t a[2][4];
            ldsm4(a[0], Ap + (uint32_t)((m0      + l16)*LDK + ko + koff)*2);
            ldsm4(a[1], Ap + (uint32_t)((m0 + 16 + l16)*LDK + ko + koff)*2);
            #pragma unroll
            for (int jp = 0; jp < NTILE/32; jp++){
                uint32_t br[4];
                ldsm4(br, Bp + (uint32_t)((n0 + jp*16 + l16)*LDK + ko + koff)*2);
                mma16816(acc[0][2*jp  ], a[0], br[0], br[2]);
                mma16816(acc[0][2*jp+1], a[0], br[1], br[3]);
                mma16816(acc[1][2*jp  ], a[1], br[0], br[2]);
                mma16816(acc[1][2*jp+1], a[1], br[1], br[3]);
            }
        }
    };

    for (int c = 0; c < NC; c += 2){
        asm volatile("cp.async.wait_group 0;" ::: "memory");
        __syncthreads();
        if (c + 2 < NC){
            stage(c + 2);
            stage(c + 3);
            asm volatile("cp.async.commit_group;" ::: "memory");
        }
        compute(c);
        compute(c + 1);
    }

    // ------------------------------ epilogue ---------------------------------
    int rowbase = blockIdx.y*128 + m0 + g;

    if (VSPLIT && (int)blockIdx.x*NTILE >= 1024){
        #pragma unroll
        for (int im = 0; im < 2; im++){
            int r0 = rowbase + im*16;
            int bq = r0 >> 10, t = r0 & 1023;
            #pragma unroll
            for (int jn = 0; jn < NFR; jn++){
                int gcol = blockIdx.x*NTILE + n0 + jn*8 + tig*2 - 1024;
                int nh = gcol >> 6, hh = gcol & 63;
                __half* vp = vtout + ((long)(bq*8 + nh)*64 + hh)*SS + t;
                vp[0]      = __float2half_rn(acc[im][jn][0] * alpha);
                vp[SS]     = __float2half_rn(acc[im][jn][1] * alpha);
                vp[8]      = __float2half_rn(acc[im][jn][2] * alpha);
                vp[SS + 8] = __float2half_rn(acc[im][jn][3] * alpha);
            }
        }
        return;
    }

    OT* Cb = C + (long)blockIdx.x*NTILE;
    const RT* Rb = resid ? resid + (long)blockIdx.x*NTILE : nullptr;
    const float* Bi = bias  ? bias + (long)blockIdx.x*NTILE : nullptr;

    auto wr = [&](int r, int col, float v0, float v1){
        v0 *= alpha; v1 *= alpha;
        if (Bi){ v0 += Bi[col]; v1 += Bi[col+1]; }
        if (Rb){
            if (sizeof(RT) == 2){
                __half2 rr = *(const __half2*)((const __half*)Rb + (long)r*ldr + col);
                float2 rf = __half22float2(rr);
                v0 += rf.x; v1 += rf.y;
            } else {
                float2 rr = *(const float2*)((const float*)Rb + (long)r*ldr + col);
                v0 += rr.x; v1 += rr.y;
            }
        }
        if (RELU){ v0 = fmaxf(v0, 0.f); v1 = fmaxf(v1, 0.f); }
        if (sizeof(OT) == 2){
            __half2 o = __floats2half2_rn(v0, v1);
            *(__half2*)((__half*)Cb + (long)r*ldc + col) = o;
        } else {
            float2 o; o.x = v0; o.y = v1;
            *(float2*)((float*)Cb + (long)r*ldc + col) = o;
        }
    };

    #pragma unroll
    for (int im = 0; im < 2; im++){
        int r0 = rowbase + im*16;
        #pragma unroll
        for (int jn = 0; jn < NFR; jn++){
            int col = n0 + jn*8 + tig*2;
            wr(r0,     col, acc[im][jn][0], acc[im][jn][1]);
            wr(r0 + 8, col, acc[im][jn][2], acc[im][jn][3]);
        }
    }
}

// ------------------- flash attention: fused S/softmax/PV --------------------
// grid (4 f-tiles, 64 bn), 256 threads, 1 block/SM. Q tile 256 rows (32/warp),
// t-tiles 64, 4-stage KV ring, barrier + wait_group only every 2 iterations.
// (R14 configuration — best measured.)
__global__ __launch_bounds__(256, 1)
void flash_kernel(const __half* __restrict__ qkv, const __half* __restrict__ vt,
                  const float* __restrict__ biasl, __half* __restrict__ attn)
{
    extern __shared__ __half sm[];
    char* smb = (char*)sm;
    uint32_t sQ = smem_u32(sm);
    uint32_t sK = sQ + OFF_K;
    uint32_t sV = sQ + OFF_V;
    uint32_t sB = sQ + OFF_B;

    int tid = threadIdx.x, wid = tid >> 5, lane = tid & 31;
    int g = lane >> 2, tig = lane & 3;
    int l16 = lane & 15, koff = (lane >> 4) * 8;
    int bn = blockIdx.y, b = bn >> 3, n = bn & 7;
    int f0 = blockIdx.x * 256;

    const __half* Qg = qkv + ((long)b*SS + f0)*QKVLD + n*64;
    const __half* Kg = qkv + (long)b*SS*QKVLD + 512 + n*64;
    const __half* Vg = vt + (long)bn*HDIM*SS;
    const float*  bi = biasl + (long)b*SS;

    auto stageKV = [&](int it2, int s){
        int t0 = it2*64;
        const __half* kp = Kg + (long)t0*QKVLD;
        uint32_t dk = sK + (uint32_t)s*64*LDQ*2;
        #pragma unroll
        for (int j = 0; j < 2; j++){
            int seg = j*256 + tid; int r = seg >> 3, c = seg & 7;
            cpa16(dk + (uint32_t)(r*LDQ + c*8)*2, kp + (long)r*QKVLD + c*8);
        }
        const __half* vp = Vg + t0;
        uint32_t dv = sV + (uint32_t)s*64*LDV*2;
        #pragma unroll
        for (int j = 0; j < 2; j++){
            int seg = j*256 + tid; int r = seg >> 3, c = seg & 7;
            cpa16(dv + (uint32_t)(r*LDV + c*8)*2, vp + (long)r*SS + c*8);
        }
        if (tid < 16)
            cpa16(sB + (uint32_t)s*256 + tid*16, bi + t0 + tid*4);
    };

    // prologue: Q (256x64) + KV tiles 0,1 in one commit group
    #pragma unroll
    for (int j = 0; j < 8; j++){
        int seg = j*256 + tid; int r = seg >> 3, c = seg & 7;
        cpa16(sQ + (uint32_t)(r*LDQ + c*8)*2, Qg + (long)r*QKVLD + c*8);
    }
    stageKV(0, 0);
    stageKV(1, 1);
    asm volatile("cp.async.commit_group;" ::: "memory");

    int m0 = wid*32;                 // 32 Q rows per warp
    float acc[2][8][4];
    #pragma unroll
    for (int i = 0; i < 2; i++)
        #pragma unroll
        for (int j = 0; j < 8; j++)
            #pragma unroll
            for (int e = 0; e < 4; e++) acc[i][j][e] = 0.f;
    float accL[2][4] = {{0.f,0.f,0.f,0.f},{0.f,0.f,0.f,0.f}};

    uint32_t qf[2][4][4];

    auto compute = [&](int it2){
        uint32_t Kp = sK + (uint32_t)(it2 & 3)*64*LDQ*2;
        uint32_t Vp = sV + (uint32_t)(it2 & 3)*64*LDV*2;
        const float* bp = (const float*)(smb + (OFF_B + (it2 & 3)*256));

        float sv[2][8][4];
        #pragma unroll
        for (int im = 0; im < 2; im++)
            #pragma unroll
            for (int nt = 0; nt < 8; nt++)
                #pragma unroll
                for (int e = 0; e < 4; e++) sv[im][nt][e] = 0.f;

        #pragma unroll
        for (int kc = 0; kc < 4; kc++){
            #pragma unroll
            for (int np = 0; np < 4; np++){
                uint32_t br[4];
                ldsm4(br, Kp + (uint32_t)((np*16 + l16)*LDQ + kc*16 + koff)*2);
                mma16816(sv[0][2*np  ], qf[0][kc], br[0], br[2]);
                mma16816(sv[0][2*np+1], qf[0][kc], br[1], br[3]);
                mma16816(sv[1][2*np  ], qf[1][kc], br[0], br[2]);
                mma16816(sv[1][2*np+1], qf[1][kc], br[1], br[3]);
            }
        }

        // per-kc2: exp (fp16) for 2 nt rows, then ones-MMA + PV MMAs
        #pragma unroll
        for (int kc2 = 0; kc2 < 4; kc2++){
            int nt0 = 2*kc2, nt1 = 2*kc2 + 1;
            float2 bv0 = *(const float2*)(bp + nt0*8 + tig*2);
            float2 bv1 = *(const float2*)(bp + nt1*8 + tig*2);
            uint32_t ph[2][4];
            #pragma unroll
            for (int im = 0; im < 2; im++){
                ph[im][0] = hexp2_2(h2pack(sv[im][nt0][0] + bv0.x,
                                           sv[im][nt0][1] + bv0.y));
                ph[im][1] = hexp2_2(h2pack(sv[im][nt0][2] + bv0.x,
                                           sv[im][nt0][3] + bv0.y));
                ph[im][2] = hexp2_2(h2pack(sv[im][nt1][0] + bv1.x,
                                           sv[im][nt1][1] + bv1.y));
                ph[im][3] = hexp2_2(h2pack(sv[im][nt1][2] + bv1.x,
                                           sv[im][nt1][3] + bv1.y));
            }
            mma16816(accL[0], ph[0], ONES2, ONES2);
            mma16816(accL[1], ph[1], ONES2, ONES2);
            #pragma unroll
            for (int jp = 0; jp < 4; jp++){
                uint32_t br[4];
                ldsm4(br, Vp + (uint32_t)((jp*16 + l16)*LDV + kc2*16 + koff)*2);
                mma16816(acc[0][2*jp  ], ph[0], br[0], br[2]);
                mma16816(acc[0][2*jp+1], ph[0], br[1], br[3]);
                mma16816(acc[1][2*jp  ], ph[1], br[0], br[2]);
                mma16816(acc[1][2*jp+1], ph[1], br[1], br[3]);
            }
        }
    };

    for (int it = 0; it < 16; it += 2){
        asm volatile("cp.async.wait_group 0;" ::: "memory");
        __syncthreads();
        if (it + 2 < 16){
            stageKV(it + 2, (it + 2) & 3);
            stageKV(it + 3, (it + 3) & 3);
            asm volatile("cp.async.commit_group;" ::: "memory");
        }
        if (it == 0){
            const __half2 s8 = __float2half2_rn(0.125f * LOG2E);
            #pragma unroll
            for (int im = 0; im < 2; im++)
                #pragma unroll
                for (int kc = 0; kc < 4; kc++){
                    ldsm4(qf[im][kc],
                          sQ + (uint32_t)((m0 + im*16 + l16)*LDQ + kc*16 + koff)*2);
                    #pragma unroll
                    for (int e = 0; e < 4; e++){
                        __half2 v = *(__half2*)&qf[im][kc][e];
                        v = __hmul2(v, s8);
                        qf[im][kc][e] = *(uint32_t*)&v;
                    }
                }
        }
        compute(it);
        compute(it + 1);
    }

    #pragma unroll
    for (int im = 0; im < 2; im++){
        float i0 = __frcp_rn(accL[im][0]), i1 = __frcp_rn(accL[im][2]);
        int row0 = f0 + m0 + im*16 + g;
        __half* op0 = attn + ((long)b*SS + row0    )*DD + n*64;
        __half* op1 = attn + ((long)b*SS + row0 + 8)*DD + n*64;
        #pragma unroll
        for (int jn = 0; jn < 8; jn++){
            int col = jn*8 + tig*2;
            *(__half2*)(op0 + col) = __floats2half2_rn(acc[im][jn][0]*i0,
                                                       acc[im][jn][1]*i0);
            *(__half2*)(op1 + col) = __floats2half2_rn(acc[im][jn][2]*i1,
                                                       acc[im][jn][3]*i1);
        }
    }
}

// --- weight transposes + bias prescale + LN1 fused into ONE launch ----------
// blocks [0,3072): transposes; [3072,3104): bias*log2e; [3104,7200): LN1
__global__ void prep_all(const float* __restrict__ wq, const float* __restrict__ wk,
                         const float* __restrict__ wv, const float* __restrict__ wo,
                         const float* __restrict__ w1, const float* __restrict__ w2,
                         __half* __restrict__ wqkvt, __half* __restrict__ wot,
                         __half* __restrict__ w1t, __half* __restrict__ w2t,
                         const float* __restrict__ abias, float* __restrict__ biasl,
                         const float* __restrict__ inputs,
                         const float* __restrict__ ln1_g,
                         const float* __restrict__ ln1_b,
                         __half* __restrict__ y)
{
    int bid = blockIdx.x;
    int tid = threadIdx.y*32 + threadIdx.x;

    if (bid >= 3104){
        int sub = tid >> 7;
        int t = tid & 127;
        long row = (long)(bid - 3104)*2 + sub;
        const float4* x4 = (const float4*)(inputs + row*DD);
        __half2* o2 = (__half2*)(y + row*DD);
        float4 v = x4[t];

        float s = v.x + v.y + v.z + v.w;
        #pragma unroll
        for (int o = 16; o; o >>= 1) s += __shfl_xor_sync(0xffffffffu, s, o);
        __shared__ float redA[2][4];
        if ((t & 31) == 0) redA[sub][t >> 5] = s;
        __syncthreads();
        s = redA[sub][0] + redA[sub][1] + redA[sub][2] + redA[sub][3];
        float mean = s * (1.0f / DD);

        float dx = v.x - mean, dy = v.y - mean, dz = v.z - mean, dw = v.w - mean;
        float vs = dx*dx + dy*dy + dz*dz + dw*dw;
        #pragma unroll
        for (int o = 16; o; o >>= 1) vs += __shfl_xor_sync(0xffffffffu, vs, o);
        __shared__ float redB[2][4];
        if ((t & 31) == 0) redB[sub][t >> 5] = vs;
        __syncthreads();
        vs = redB[sub][0] + redB[sub][1] + redB[sub][2] + redB[sub][3];
        float rstd = rsqrtf(vs * (1.0f / DD) + EPSLN);

        float4 g4 = ((const float4*)ln1_g)[t];
        float4 b4 = ((const float4*)ln1_b)[t];
        o2[2*t]   = __floats2half2_rn(g4.x*dx*rstd + b4.x, g4.y*dy*rstd + b4.y);
        o2[2*t+1] = __floats2half2_rn(g4.z*dz*rstd + b4.z, g4.w*dw*rstd + b4.w);
        return;
    }
    if (bid >= 3072){
        int idx = (bid - 3072)*256 + tid;
        biasl[idx] = abias[idx] * LOG2E;
        return;
    }

    __shared__ float t[32][33];
    const float* in; __half* out; int ld_in, ld_out, bx, by;
    if (bid < 768){
        int s = bid >> 8, r = bid & 255;
        in = (s == 0) ? wq : (s == 1) ? wk : wv;
        out = wqkvt + (long)s*512*512;
        ld_in = 512; ld_out = 512; bx = r & 15; by = r >> 4;
    } else if (bid < 1024){
        int r = bid - 768;
        in = wo; out = wot; ld_in = 512; ld_out = 512; bx = r & 15; by = r >> 4;
    } else if (bid < 2048){
        int r = bid - 1024;
        in = w1; out = w1t; ld_in = 2048; ld_out = 512; bx = r & 63; by = r >> 6;
    } else {
        int r = bid - 2048;
        in = w2; out = w2t; ld_in = 512; ld_out = 2048; bx = r & 15; by = r >> 4;
    }
    int r0 = by*32, c0 = bx*32;
    int tx = threadIdx.x, ty = threadIdx.y;
    #pragma unroll
    for (int k = 0; k < 32; k += 8)
        t[ty+k][tx] = in[(long)(r0+ty+k)*ld_in + c0+tx];
    __syncthreads();
    #pragma unroll
    for (int k = 0; k < 32; k += 8)
        out[(long)(c0+ty+k)*ld_out + r0+tx] = __float2half_rn(t[tx][ty+k]);
}

// ---------- LN2: fp16 in -> fp16 out, two rows per 256-thread block ----------
__global__ void ln2_kernel(const __half* __restrict__ in,
                           const float* __restrict__ gamma,
                           const float* __restrict__ beta,
                           __half* __restrict__ out)
{
    int tid = threadIdx.x;
    int sub = tid >> 7;
    int t = tid & 127;
    long row = (long)blockIdx.x*2 + sub;
    const __half2* x2 = (const __half2*)(in + row*DD);
    __half2* o2 = (__half2*)(out + row*DD);
    float2 a = __half22float2(x2[2*t]);
    float2 bb = __half22float2(x2[2*t+1]);

    float s = a.x + a.y + bb.x + bb.y;
    #pragma unroll
    for (int o = 16; o; o >>= 1) s += __shfl_xor_sync(0xffffffffu, s, o);
    __shared__ float redA[2][4];
    if ((t & 31) == 0) redA[sub][t >> 5] = s;
    __syncthreads();
    s = redA[sub][0] + redA[sub][1] + redA[sub][2] + redA[sub][3];
    float mean = s * (1.0f / DD);

    float dx = a.x - mean, dy = a.y - mean, dz = bb.x - mean, dw = bb.y - mean;
    float vs = dx*dx + dy*dy + dz*dz + dw*dw;
    #pragma unroll
    for (int o = 16; o; o >>= 1) vs += __shfl_xor_sync(0xffffffffu, vs, o);
    __shared__ float redB[2][4];
    if ((t & 31) == 0) redB[sub][t >> 5] = vs;
    __syncthreads();
    vs = redB[sub][0] + redB[sub][1] + redB[sub][2] + redB[sub][3];
    float rstd = rsqrtf(vs * (1.0f / DD) + EPSLN);

    float4 g4 = ((const float4*)gamma)[t];
    float4 b4 = ((const float4*)beta)[t];
    o2[2*t]   = __floats2half2_rn(g4.x*dx*rstd + b4.x, g4.y*dy*rstd + b4.y);
    o2[2*t+1] = __floats2half2_rn(g4.z*dz*rstd + b4.z, g4.w*dw*rstd + b4.w);
}

// ------------------------------- launch ---------------------------------------
extern "C" void kernel_launch(void* const* d_in, const int* in_sizes, int n_in,
                              void* d_out, int out_size)
{
    const float* inputs = (const float*)d_in[0];
    const float* abias  = (const float*)d_in[1];
    const float* ln1_g  = (const float*)d_in[2];
    const float* ln1_b  = (const float*)d_in[3];
    const float* wq     = (const float*)d_in[4];
    const float* wk     = (const float*)d_in[5];
    const float* wv     = (const float*)d_in[6];
    const float* wo     = (const float*)d_in[7];
    const float* ln2_g  = (const float*)d_in[8];
    const float* ln2_b  = (const float*)d_in[9];
    const float* w1     = (const float*)d_in[10];
    const float* b1     = (const float*)d_in[11];
    const float* w2     = (const float*)d_in[12];
    const float* b2     = (const float*)d_in[13];

    __half *y,*qkv,*at,*xh,*h,*vt,*wqkvt,*wot,*w1t,*w2t;
    float *biasl;
    cudaGetSymbolAddress((void**)&y,   g_y);
    cudaGetSymbolAddress((void**)&qkv, g_qkv);
    cudaGetSymbolAddress((void**)&at,  g_attn);
    cudaGetSymbolAddress((void**)&xh,  g_xh);
    cudaGetSymbolAddress((void**)&h,   g_h);
    cudaGetSymbolAddress((void**)&vt,  g_vt);
    cudaGetSymbolAddress((void**)&wqkvt, g_wqkvt);
    cudaGetSymbolAddress((void**)&wot, g_wot);
    cudaGetSymbolAddress((void**)&w1t, g_w1t);
    cudaGetSymbolAddress((void**)&w2t, g_w2t);
    cudaGetSymbolAddress((void**)&biasl, g_biasl);
    float* out = (float*)d_out;

    const int GEMM_SMEM  = 4 * (128 + 128) * 40 * 2;   // 81920
    const int FLASH_SMEM = FLASH_SMEM_BYTES;           // 111616
    cudaFuncSetAttribute(hgemm<128,false,__half,float ,true >,
        cudaFuncAttributeMaxDynamicSharedMemorySize, GEMM_SMEM);
    cudaFuncSetAttribute(hgemm<128,false,__half,float ,false>,
        cudaFuncAttributeMaxDynamicSharedMemorySize, GEMM_SMEM);
    cudaFuncSetAttribute(hgemm<128,true ,__half,float ,false>,
        cudaFuncAttributeMaxDynamicSharedMemorySize, GEMM_SMEM);
    cudaFuncSetAttribute(hgemm<128,false,float ,__half,false>,
        cudaFuncAttributeMaxDynamicSharedMemorySize, GEMM_SMEM);
    cudaFuncSetAttribute(flash_kernel,
        cudaFuncAttributeMaxDynamicSharedMemorySize, FLASH_SMEM);

    // transposes + bias prescale + LN1, one launch
    prep_all<<<7200, dim3(32,8)>>>(wq, wk, wv, wo, w1, w2,
                                   wqkvt, wot, w1t, w2t, abias, biasl,
                                   inputs, ln1_g, ln1_b, y);

    // fused QKV projection; V tiles written transposed into vt
    hgemm<128,false,__half,float,true><<<dim3(12,64,1), 256, GEMM_SMEM>>>(
        y, DD, wqkvt, DD, qkv, QKVLD, DD, nullptr, nullptr, 0, 1.0f, vt);

    // flash attention -> attn (half); Q tile 256, 4-stage ring (R14 config)
    flash_kernel<<<dim3(4,64,1), 256, FLASH_SMEM>>>(qkv, vt, biasl, at);

    // xh = attn . wo + inputs  (fp16 out, fp32 residual)
    hgemm<128,false,__half,float,false><<<dim3(4,64,1), 256, GEMM_SMEM>>>(
        at, DD, wot, DD, xh, DD, DD, nullptr, inputs, DD, 1.0f, nullptr);

    // LN2: xh -> y (half), two rows per block
    ln2_kernel<<<ROWS/2, 256>>>(xh, ln2_g, ln2_b, y);

    // FFN
    hgemm<128,true,__half,float,false><<<dim3(16,64,1), 256, GEMM_SMEM>>>(
        y, DD, w1t, DD, h, FF, DD, b1, nullptr, 0, 1.0f, nullptr);
    hgemm<128,false,float,__half,false><<<dim3(4,64,1), 256, GEMM_SMEM>>>(
        h, FF, w2t, FF, out, DD, FF, b2, xh, DD, 1.0f, nullptr);
}